// round 3
// baseline (speedup 1.0000x reference)
#include <cuda_runtime.h>
#include <math.h>
#include <stdint.h>

// ---------------------------------------------------------------------------
// Problem constants
// ---------------------------------------------------------------------------
namespace {
constexpr int Bb   = 2;
constexpr int Hh   = 512;
constexpr int Ww   = 512;
constexpr int Np   = Hh * Ww;
constexpr int Cc   = 48;
constexpr int C3   = 144;
constexpr int HID  = 127;
constexpr int HID2 = 254;
constexpr int NPART  = 1024;
constexpr int CHUNK  = Np / NPART;
constexpr int GSLOTS = 48 * 48 + 96;
// GDFN fused kernel geometry
constexpr int TW  = 128;            // output pixels per tile (one row segment)
constexpr int PX  = 390;            // 3 rows x 130 halo pixels
constexpr int PXD = 420;            // padded pixel stride (mod 32 == 4)
}

// ---------------------------------------------------------------------------
// Scratch
// ---------------------------------------------------------------------------
__device__ float g_patch[(size_t)Bb * Cc * Np];
__device__ float g_qkv0 [(size_t)Bb * C3 * Np];
__device__ float g_qkv  [(size_t)Bb * C3 * Np];
__device__ float g_first[(size_t)Bb * Cc * Np];
__device__ float g_part [(size_t)Bb * NPART * GSLOTS];
__device__ float g_gfin [Bb * GSLOTS];
__device__ float g_M    [Bb * 48 * 48];

// ---------------------------------------------------------------------------
// tf32 helpers
// ---------------------------------------------------------------------------
__device__ __forceinline__ void tf32_split(float f, uint32_t& h, uint32_t& l) {
  uint32_t hu = __float_as_uint(f) & 0xFFFFE000u;
  h = hu;
  l = __float_as_uint(f - __uint_as_float(hu));
}
__device__ __forceinline__ void mma_tf32(float c[4], uint32_t a0, uint32_t a1,
                                         uint32_t a2, uint32_t a3, uint32_t b0,
                                         uint32_t b1) {
  asm volatile(
      "mma.sync.aligned.m16n8k8.row.col.f32.tf32.tf32.f32 "
      "{%0,%1,%2,%3}, {%4,%5,%6,%7}, {%8,%9}, {%0,%1,%2,%3};"
      : "+f"(c[0]), "+f"(c[1]), "+f"(c[2]), "+f"(c[3])
      : "r"(a0), "r"(a1), "r"(a2), "r"(a3), "r"(b0), "r"(b1));
}
// 3-pass (hi*hi + hi*lo + lo*hi) fp32-grade mma from raw f32 operands
__device__ __forceinline__ void mma3(float c[4], float a0f, float a1f,
                                     float a2f, float a3f, float b0f,
                                     float b1f) {
  uint32_t ah0, al0, ah1, al1, ah2, al2, ah3, al3, bh0, bl0, bh1, bl1;
  tf32_split(a0f, ah0, al0);
  tf32_split(a1f, ah1, al1);
  tf32_split(a2f, ah2, al2);
  tf32_split(a3f, ah3, al3);
  tf32_split(b0f, bh0, bl0);
  tf32_split(b1f, bh1, bl1);
  mma_tf32(c, ah0, ah1, ah2, ah3, bh0, bh1);
  mma_tf32(c, ah0, ah1, ah2, ah3, bl0, bl1);
  mma_tf32(c, al0, al1, al2, al3, bh0, bh1);
}

// ---------------------------------------------------------------------------
// K1: patch embed conv 3x3, 3 -> 48
// ---------------------------------------------------------------------------
__global__ __launch_bounds__(128) void k_pe(const float* __restrict__ x,
                                            const float* __restrict__ pw,
                                            float* __restrict__ out) {
  __shared__ float ws[48 * 27];
  __shared__ float si[3][3][514];
  int b = blockIdx.x / Hh, y = blockIdx.x % Hh;
  int tid = threadIdx.x;
  for (int i = tid; i < 48 * 27; i += 128) ws[i] = pw[i];
  for (int i = tid; i < 3 * 3 * 512; i += 128) {
    int ch = i / 1536, r = (i / 512) % 3, xx = i % 512;
    int yy = y - 1 + r;
    float v = (yy >= 0 && yy < Hh)
                  ? x[((size_t)(b * 3 + ch) * Hh + yy) * Ww + xx]
                  : 0.f;
    si[ch][r][xx + 1] = v;
  }
  if (tid < 9) {
    int ch = tid / 3, r = tid % 3;
    si[ch][r][0] = 0.f;
    si[ch][r][513] = 0.f;
  }
  __syncthreads();

  int x0 = tid * 4;
  float rv[3][3][6];
#pragma unroll
  for (int ch = 0; ch < 3; ch++)
#pragma unroll
    for (int r = 0; r < 3; r++)
#pragma unroll
      for (int d = 0; d < 6; d++) rv[ch][r][d] = si[ch][r][x0 + d];

  float* op = out + (size_t)b * Cc * Np + (size_t)y * Ww + x0;
  for (int o = 0; o < 48; o++) {
    float a0 = 0.f, a1 = 0.f, a2 = 0.f, a3 = 0.f;
#pragma unroll
    for (int ch = 0; ch < 3; ch++)
#pragma unroll
      for (int r = 0; r < 3; r++)
#pragma unroll
        for (int dx = 0; dx < 3; dx++) {
          float w = ws[o * 27 + ch * 9 + r * 3 + dx];
          a0 = fmaf(rv[ch][r][dx + 0], w, a0);
          a1 = fmaf(rv[ch][r][dx + 1], w, a1);
          a2 = fmaf(rv[ch][r][dx + 2], w, a2);
          a3 = fmaf(rv[ch][r][dx + 3], w, a3);
        }
    *reinterpret_cast<float4*>(op + (size_t)o * Np) = make_float4(a0, a1, a2, a3);
  }
}

// ---------------------------------------------------------------------------
// Tensor-core pixel GEMM; f32 in smem, tf32 hi/lo split in registers.
// ---------------------------------------------------------------------------
template <int K, int KC, int BN, bool LN, bool RES, bool PBW>
__global__ __launch_bounds__((BN / 16) * 64) void k_tgemm(
    const float* __restrict__ in, int in_cs, int in_co,
    const float* __restrict__ w,
    const float* __restrict__ nw, const float* __restrict__ nb,
    const float* __restrict__ res, int res_cs,
    float* __restrict__ out, int out_cs, int CO) {
  constexpr int MT = BN / 16;
  constexpr int NTH = MT * 64;
  constexpr int SBd = 132;
  constexpr int SAd = BN + 4;
  constexpr int KSTEPS = KC / 8;

  extern __shared__ float smf[];
  float* sB = smf;                     // [KC][SBd]
  float* sA = smf + KC * SBd;          // [KC][SAd]
  float* tail = sA + KC * SAd;
  float* mu = tail;        // 128
  float* rs = tail + 128;  // 128
  float* snw = tail + 256;
  float* snb = tail + 304;

  int tid = threadIdx.x;
  int wid = tid / 32, lane = tid % 32;
  int warp_m = wid % MT, warp_n = wid / MT;
  int n0 = warp_n * 64;
  int o0 = blockIdx.x * BN;
  int pb = blockIdx.y;
  int b = pb / (Np / 128);
  int n0g = (pb % (Np / 128)) * 128;

  const float* ip = in + ((size_t)b * in_cs + in_co) * Np + n0g;
  const float* wp = PBW ? (w + (size_t)b * CO * K) : w;

  float acc[8][4];
#pragma unroll
  for (int j = 0; j < 8; j++)
#pragma unroll
    for (int i = 0; i < 4; i++) acc[j][i] = 0.f;

  for (int k0 = 0; k0 < K; k0 += KC) {
    for (int i = tid; i < KC * BN; i += NTH) {
      int k = i / BN, m = i % BN;
      int o = o0 + m, kk = k0 + k;
      sA[k * SAd + m] = (o < CO && kk < K) ? wp[(size_t)o * K + kk] : 0.f;
    }
    if constexpr (LN) {
      for (int i = tid; i < KC * 128; i += NTH) {
        int k = i >> 7, j = i & 127;
        sB[k * SBd + j] = ip[(size_t)k * Np + j];
      }
      for (int i = tid; i < K; i += NTH) {
        snw[i] = nw[i];
        snb[i] = nb[i];
      }
      __syncthreads();
      for (int j = tid; j < 128; j += NTH) {
        float s = 0.f;
#pragma unroll 8
        for (int k = 0; k < K; k++) s += sB[k * SBd + j];
        float m = s * (1.f / (float)K);
        float v = 0.f;
#pragma unroll 8
        for (int k = 0; k < K; k++) {
          float d = sB[k * SBd + j] - m;
          v = fmaf(d, d, v);
        }
        mu[j] = m;
        rs[j] = rsqrtf(v * (1.f / (float)K) + 1e-5f);
      }
      __syncthreads();
      for (int i = tid; i < KC * 128; i += NTH) {
        int k = i >> 7, j = i & 127;
        sB[k * SBd + j] = (sB[k * SBd + j] - mu[j]) * rs[j] * snw[k] + snb[k];
      }
    } else {
      for (int i = tid; i < KC * 128; i += NTH) {
        int k = i >> 7, j = i & 127;
        int kk = k0 + k;
        sB[k * SBd + j] = (kk < K) ? ip[(size_t)kk * Np + j] : 0.f;
      }
    }
    __syncthreads();

    int tg = lane & 3, gr = lane >> 2;
#pragma unroll
    for (int ks = 0; ks < KSTEPS; ks++) {
      int kr0 = ks * 8 + tg;
      float a0f = sA[kr0 * SAd + warp_m * 16 + gr];
      float a1f = sA[kr0 * SAd + warp_m * 16 + gr + 8];
      float a2f = sA[(kr0 + 4) * SAd + warp_m * 16 + gr];
      float a3f = sA[(kr0 + 4) * SAd + warp_m * 16 + gr + 8];
#pragma unroll
      for (int j = 0; j < 8; j++) {
        float b0f = sB[kr0 * SBd + n0 + j * 8 + gr];
        float b1f = sB[(kr0 + 4) * SBd + n0 + j * 8 + gr];
        mma3(acc[j], a0f, a1f, a2f, a3f, b0f, b1f);
      }
    }
    if (k0 + KC < K) __syncthreads();
  }

  int gr = lane >> 2, tg = lane & 3;
#pragma unroll
  for (int j = 0; j < 8; j++) {
    int nn = n0 + j * 8 + 2 * tg;
#pragma unroll
    for (int h = 0; h < 2; h++) {
      int o = o0 + warp_m * 16 + gr + h * 8;
      if (o < CO) {
        float2 r = make_float2(acc[j][h * 2], acc[j][h * 2 + 1]);
        float* optr = out + ((size_t)b * out_cs + o) * Np + n0g + nn;
        if constexpr (RES) {
          const float2 q = *reinterpret_cast<const float2*>(
              res + ((size_t)b * res_cs + o) * Np + n0g + nn);
          r.x += q.x;
          r.y += q.y;
        }
        *reinterpret_cast<float2*>(optr) = r;
      }
    }
  }
}

// ---------------------------------------------------------------------------
// Depthwise 3x3 conv (SAME), 4 pixels per thread (qkv path).
// ---------------------------------------------------------------------------
__global__ __launch_bounds__(256) void k_dw(const float* __restrict__ in,
                                            const float* __restrict__ w9,
                                            float* __restrict__ out, int Cn) {
  int idx = blockIdx.x * 256 + threadIdx.x;
  int total = Bb * Cn * (Np / 4);
  if (idx >= total) return;
  int xq = idx % (Ww / 4);
  int t = idx / (Ww / 4);
  int y = t % Hh; t /= Hh;
  int c = t % Cn;
  int b = t / Cn;
  int x0 = xq * 4;

  float wv[9];
#pragma unroll
  for (int i = 0; i < 9; i++) wv[i] = w9[c * 9 + i];

  const float* base = in + ((size_t)b * Cn + c) * Np;
  float a[4] = {0.f, 0.f, 0.f, 0.f};
#pragma unroll
  for (int dy = 0; dy < 3; dy++) {
    int yy = y + dy - 1;
    if (yy < 0 || yy >= Hh) continue;
    const float* row = base + (size_t)yy * Ww;
    float v[6];
    v[0] = (x0 > 0) ? row[x0 - 1] : 0.f;
    float4 m = *reinterpret_cast<const float4*>(row + x0);
    v[1] = m.x; v[2] = m.y; v[3] = m.z; v[4] = m.w;
    v[5] = (x0 + 4 < Ww) ? row[x0 + 4] : 0.f;
#pragma unroll
    for (int dx = 0; dx < 3; dx++) {
      float wt = wv[dy * 3 + dx];
#pragma unroll
      for (int p = 0; p < 4; p++) a[p] = fmaf(v[dx + p], wt, a[p]);
    }
  }
  *reinterpret_cast<float4*>(out + ((size_t)b * Cn + c) * Np + (size_t)y * Ww + x0) =
      make_float4(a[0], a[1], a[2], a[3]);
}

// ---------------------------------------------------------------------------
// Fused GDFN: out = first + fo( gelu(dw(pi_1(LN(first)))) * dw(pi_2(LN(first))) )
// One block per 128-pixel row segment.  192 threads (6 warps).
// 8 chunks of 16 hidden pairs; h and gate live only in smem.
// ---------------------------------------------------------------------------
__global__ __launch_bounds__(192) void k_gdfn(
    const float* __restrict__ first, const float* __restrict__ nw,
    const float* __restrict__ nb, const float* __restrict__ pi_w,
    const float* __restrict__ dw_w, const float* __restrict__ fo_w,
    float* __restrict__ out) {
  extern __shared__ float smf[];
  float* sX  = smf;                 // [48][PXD]
  float* sH  = sX + 48 * PXD;       // [32][PXD]
  float* sG  = sH + 32 * PXD;       // [16][132]
  float* sPW = sG + 16 * 132;       // [48][36]  pi weights chunk, [k][m]
  float* sFW = sPW + 48 * 36;       // [16][52]  fo weights chunk, [k][m]
  float* sDW = sFW + 16 * 52;       // [32][10]  dw weights chunk
  float* mu  = sDW + 32 * 10;       // [PX]
  float* rs  = mu + PXD;            // [PX]
  float* sNW = rs + PXD;            // [48]
  float* sNB = sNW + 48;            // [48]

  int tid = threadIdx.x;
  int wid = tid / 32, lane = tid % 32;
  int tg = lane & 3, gr = lane >> 2;

  int pb = blockIdx.x;
  int b = pb / (Np / TW);
  int t = pb % (Np / TW);
  int y = t / (Ww / TW);
  int x0 = (t % (Ww / TW)) * TW;

  // ---- phase 1: load first halo + LayerNorm ----
  for (int i = tid; i < 48 * PX; i += 192) {
    int c = i / PX, p = i % PX;
    int r = p / 130, q = p % 130;
    int yy = y + r - 1, xx = x0 + q - 1;
    bool valid = (yy >= 0 && yy < Hh && xx >= 0 && xx < Ww);
    sX[c * PXD + p] =
        valid ? first[((size_t)(b * 48 + c)) * Np + (size_t)yy * Ww + xx] : 0.f;
  }
  for (int i = tid; i < 48 * (PXD - PX); i += 192) {
    int c = i / (PXD - PX), j = i % (PXD - PX);
    sX[c * PXD + PX + j] = 0.f;
  }
  for (int i = tid; i < 48; i += 192) {
    sNW[i] = nw[i];
    sNB[i] = nb[i];
  }
  __syncthreads();
  for (int p = tid; p < PX; p += 192) {
    int r = p / 130, q = p % 130;
    int yy = y + r - 1, xx = x0 + q - 1;
    bool valid = (yy >= 0 && yy < Hh && xx >= 0 && xx < Ww);
    float s = 0.f;
#pragma unroll 8
    for (int k = 0; k < 48; k++) s += sX[k * PXD + p];
    float m = s * (1.f / 48.f);
    float v = 0.f;
#pragma unroll 8
    for (int k = 0; k < 48; k++) {
      float d = sX[k * PXD + p] - m;
      v = fmaf(d, d, v);
    }
    mu[p] = m;
    rs[p] = valid ? rsqrtf(v * (1.f / 48.f) + 1e-5f) : -1.f;
  }
  __syncthreads();
  for (int i = tid; i < 48 * PX; i += 192) {
    int c = i / PX, p = i % PX;
    float r_ = rs[p];
    float xv = sX[c * PXD + p];
    sX[c * PXD + p] = (r_ < 0.f) ? 0.f : ((xv - mu[p]) * r_ * sNW[c] + sNB[c]);
  }

  // fo accumulators (persist across chunks): warp = 16 outs x 64 px
  int m0f = (wid % 3) * 16, n0f = (wid / 3) * 64;
  float accF[8][4];
#pragma unroll
  for (int j = 0; j < 8; j++)
#pragma unroll
    for (int i = 0; i < 4; i++) accF[j][i] = 0.f;

  // pi-mma warp layout: 2 m-tiles x 3 n-ranges of 136 px
  int m0p = (wid & 1) * 16, nbase = (wid >> 1) * 136;

  // ---- phase 2: hidden-channel chunks ----
  for (int ch = 0; ch < 8; ch++) {
    __syncthreads();  // protect weight/gate buffers from previous iteration
    // stage pi weights [k][m] (m: 0..15 -> x1 ch, 16..31 -> x2 ch)
    for (int i = tid; i < 48 * 32; i += 192) {
      int k = i / 32, m = i % 32;
      int hid = ch * 16 + (m & 15);
      float v = 0.f;
      if (hid < HID) {
        int row = (m < 16) ? hid : (HID + hid);
        v = pi_w[row * 48 + k];
      }
      sPW[k * 36 + m] = v;
    }
    // stage fo weights [k][m]
    for (int i = tid; i < 16 * 48; i += 192) {
      int k = i / 48, m = i % 48;
      int hid = ch * 16 + k;
      sFW[k * 52 + m] = (hid < HID) ? fo_w[m * HID + hid] : 0.f;
    }
    // stage dw weights
    for (int i = tid; i < 32 * 9; i += 192) {
      int m = i / 9, j = i % 9;
      int hid = ch * 16 + (m & 15);
      float v = 0.f;
      if (hid < HID) {
        int row = (m < 16) ? hid : (HID + hid);
        v = dw_w[row * 9 + j];
      }
      sDW[m * 10 + j] = v;
    }
    __syncthreads();

    // pi mma: h[32][PX] = PW[32][48] * X[48][PX]
    {
      float acc[17][4];
#pragma unroll
      for (int j = 0; j < 17; j++)
#pragma unroll
        for (int i = 0; i < 4; i++) acc[j][i] = 0.f;
#pragma unroll
      for (int ks = 0; ks < 6; ks++) {
        int kr0 = ks * 8 + tg;
        float a0f = sPW[kr0 * 36 + m0p + gr];
        float a1f = sPW[kr0 * 36 + m0p + gr + 8];
        float a2f = sPW[(kr0 + 4) * 36 + m0p + gr];
        float a3f = sPW[(kr0 + 4) * 36 + m0p + gr + 8];
#pragma unroll
        for (int j = 0; j < 17; j++) {
          int nn = nbase + j * 8 + gr;
          float b0f = sX[kr0 * PXD + nn];
          float b1f = sX[(kr0 + 4) * PXD + nn];
          mma3(acc[j], a0f, a1f, a2f, a3f, b0f, b1f);
        }
      }
      // write h to smem
#pragma unroll
      for (int j = 0; j < 17; j++) {
        int nn = nbase + j * 8 + 2 * tg;
        *reinterpret_cast<float2*>(sH + (m0p + gr) * PXD + nn) =
            make_float2(acc[j][0], acc[j][1]);
        *reinterpret_cast<float2*>(sH + (m0p + gr + 8) * PXD + nn) =
            make_float2(acc[j][2], acc[j][3]);
      }
    }
    __syncthreads();

    // dw 3x3 + gelu gating: gate[16][128]
    for (int task = tid; task < 16 * 32; task += 192) {
      int pp = task / 32;
      int j4 = (task % 32) * 4;
      float a1[4] = {0.f, 0.f, 0.f, 0.f};
      float a2[4] = {0.f, 0.f, 0.f, 0.f};
      const float* w1 = sDW + pp * 10;
      const float* w2 = sDW + (pp + 16) * 10;
#pragma unroll
      for (int r = 0; r < 3; r++) {
        const float* h1 = sH + pp * PXD + r * 130 + j4;
        const float* h2 = sH + (pp + 16) * PXD + r * 130 + j4;
        float v1[6], v2[6];
#pragma unroll
        for (int d = 0; d < 6; d++) {
          v1[d] = h1[d];
          v2[d] = h2[d];
        }
#pragma unroll
        for (int dx = 0; dx < 3; dx++) {
          float wa = w1[r * 3 + dx], wb = w2[r * 3 + dx];
#pragma unroll
          for (int p = 0; p < 4; p++) {
            a1[p] = fmaf(v1[dx + p], wa, a1[p]);
            a2[p] = fmaf(v2[dx + p], wb, a2[p]);
          }
        }
      }
#pragma unroll
      for (int p = 0; p < 4; p++) {
        float u = a1[p];
        sG[pp * 132 + j4 + p] =
            0.5f * u * (1.f + erff(u * 0.70710678118654752f)) * a2[p];
      }
    }
    __syncthreads();

    // fo mma accumulate: out[48][128] += FW^T[16->k] x gate[16][128]
#pragma unroll
    for (int ks = 0; ks < 2; ks++) {
      int kr0 = ks * 8 + tg;
      float a0f = sFW[kr0 * 52 + m0f + gr];
      float a1f = sFW[kr0 * 52 + m0f + gr + 8];
      float a2f = sFW[(kr0 + 4) * 52 + m0f + gr];
      float a3f = sFW[(kr0 + 4) * 52 + m0f + gr + 8];
#pragma unroll
      for (int j = 0; j < 8; j++) {
        int nn = n0f + j * 8 + gr;
        float b0f = sG[kr0 * 132 + nn];
        float b1f = sG[(kr0 + 4) * 132 + nn];
        mma3(accF[j], a0f, a1f, a2f, a3f, b0f, b1f);
      }
    }
  }

  // ---- epilogue: residual + store ----
#pragma unroll
  for (int j = 0; j < 8; j++) {
    int nn = n0f + j * 8 + 2 * tg;
#pragma unroll
    for (int h = 0; h < 2; h++) {
      int o = m0f + gr + h * 8;
      size_t base = ((size_t)(b * 48 + o)) * Np + (size_t)y * Ww + x0 + nn;
      float2 q = *reinterpret_cast<const float2*>(first + base);
      float2 r = make_float2(accF[j][h * 2] + q.x, accF[j][h * 2 + 1] + q.y);
      *reinterpret_cast<float2*>(out + base) = r;
    }
  }
}

// ---------------------------------------------------------------------------
// Gram partials (unchanged)
// ---------------------------------------------------------------------------
__global__ __launch_bounds__(96) void k_gram(const float* __restrict__ qkv,
                                             float* __restrict__ part) {
  __shared__ float sQ[48 * 33];
  __shared__ float sK[48 * 33];
  int blk = blockIdx.x;
  int b = blk / NPART, pc = blk % NPART;
  int n0 = pc * CHUNK;
  const float* q = qkv + (size_t)b * C3 * Np;
  const float* k = q + (size_t)48 * Np;
  int tid = threadIdx.x;
  int ct = tid / 12, dt = tid % 12;
  int c0 = ct * 6, d0 = dt * 4;

  float acc[6][4];
#pragma unroll
  for (int i = 0; i < 6; i++)
#pragma unroll
    for (int j = 0; j < 4; j++) acc[i][j] = 0.f;
  float nacc = 0.f;

  for (int t = 0; t < CHUNK / 32; t++) {
    int off = n0 + t * 32;
    __syncthreads();
    for (int i = tid; i < 1536; i += 96) {
      int c = i / 32, j = i % 32;
      sQ[c * 33 + j] = q[(size_t)c * Np + off + j];
      sK[c * 33 + j] = k[(size_t)c * Np + off + j];
    }
    __syncthreads();
#pragma unroll 4
    for (int j = 0; j < 32; j++) {
      float qa[6], kb[4];
#pragma unroll
      for (int i = 0; i < 6; i++) qa[i] = sQ[(c0 + i) * 33 + j];
#pragma unroll
      for (int i = 0; i < 4; i++) kb[i] = sK[(d0 + i) * 33 + j];
#pragma unroll
      for (int i = 0; i < 6; i++)
#pragma unroll
        for (int jj = 0; jj < 4; jj++)
          acc[i][jj] = fmaf(qa[i], kb[jj], acc[i][jj]);
    }
    {
      const float* s = (tid < 48) ? (sQ + tid * 33) : (sK + (tid - 48) * 33);
#pragma unroll 8
      for (int j = 0; j < 32; j++) {
        float v = s[j];
        nacc = fmaf(v, v, nacc);
      }
    }
  }
  float* pp = part + (size_t)blk * GSLOTS;
#pragma unroll
  for (int i = 0; i < 6; i++)
#pragma unroll
    for (int jj = 0; jj < 4; jj++) pp[(c0 + i) * 48 + d0 + jj] = acc[i][jj];
  pp[2304 + tid] = nacc;
}

__global__ void k_red(const float* __restrict__ part, float* __restrict__ gfin) {
  int s = blockIdx.x * blockDim.x + threadIdx.x;
  if (s >= Bb * GSLOTS) return;
  int b = s / GSLOTS, slot = s % GSLOTS;
  const float* p = part + (size_t)b * NPART * GSLOTS + slot;
  float a0 = 0.f, a1 = 0.f, a2 = 0.f, a3 = 0.f;
  for (int i = 0; i < NPART; i += 4) {
    a0 += p[(size_t)(i + 0) * GSLOTS];
    a1 += p[(size_t)(i + 1) * GSLOTS];
    a2 += p[(size_t)(i + 2) * GSLOTS];
    a3 += p[(size_t)(i + 3) * GSLOTS];
  }
  gfin[s] = (a0 + a1) + (a2 + a3);
}

__global__ __launch_bounds__(256) void k_att(const float* __restrict__ gfin,
                                             const float* __restrict__ temp,
                                             const float* __restrict__ po,
                                             float* __restrict__ M) {
  __shared__ float sG[2304];
  __shared__ float sAt[2304];
  __shared__ float snq[48], snk[48];
  int b = blockIdx.x, tid = threadIdx.x;
  const float* g = gfin + (size_t)b * GSLOTS;
  for (int i = tid; i < 2304; i += 256) sG[i] = g[i];
  if (tid < 96) {
    float nv = sqrtf(fmaxf(g[2304 + tid], 0.f));
    nv = fmaxf(nv, 1e-12f);
    if (tid < 48) snq[tid] = nv;
    else snk[tid - 48] = nv;
  }
  __syncthreads();
  float tv = temp[0];
  for (int i = tid; i < 2304; i += 256) {
    int c = i / 48, d = i % 48;
    sG[i] = sG[i] * tv / (snq[c] * snk[d]);
  }
  __syncthreads();
  if (tid < 48) {
    float mx = -1e30f;
    for (int d = 0; d < 48; d++) mx = fmaxf(mx, sG[tid * 48 + d]);
    float s = 0.f;
    for (int d = 0; d < 48; d++) {
      float e = expf(sG[tid * 48 + d] - mx);
      sAt[tid * 48 + d] = e;
      s += e;
    }
    float inv = 1.f / s;
    for (int d = 0; d < 48; d++) sAt[tid * 48 + d] *= inv;
  }
  __syncthreads();
  for (int i = tid; i < 2304; i += 256) {
    int o = i / 48, d = i % 48;
    float a = 0.f;
#pragma unroll 8
    for (int c = 0; c < 48; c++) a = fmaf(po[o * 48 + c], sAt[c * 48 + d], a);
    M[(size_t)b * 2304 + i] = a;
  }
}

// ---------------------------------------------------------------------------
// Launch
// ---------------------------------------------------------------------------
extern "C" void kernel_launch(void* const* d_in, const int* in_sizes, int n_in,
                              void* d_out, int out_size) {
  (void)in_sizes; (void)n_in; (void)out_size;
  const float* x      = (const float*)d_in[0];
  const float* pe_w   = (const float*)d_in[1];
  const float* n1_w   = (const float*)d_in[2];
  const float* n1_b   = (const float*)d_in[3];
  const float* temp   = (const float*)d_in[4];
  const float* qkv_w  = (const float*)d_in[5];
  const float* qkv_dw = (const float*)d_in[6];
  const float* po_w   = (const float*)d_in[7];
  const float* n2_w   = (const float*)d_in[8];
  const float* n2_b   = (const float*)d_in[9];
  const float* pi_w   = (const float*)d_in[10];
  const float* ffn_dw = (const float*)d_in[11];
  const float* fo_w   = (const float*)d_in[12];
  float* out = (float*)d_out;

  float *patch, *qkv0, *qkv, *first, *part, *gfin, *M;
  cudaGetSymbolAddress((void**)&patch, g_patch);
  cudaGetSymbolAddress((void**)&qkv0,  g_qkv0);
  cudaGetSymbolAddress((void**)&qkv,   g_qkv);
  cudaGetSymbolAddress((void**)&first, g_first);
  cudaGetSymbolAddress((void**)&part,  g_part);
  cudaGetSymbolAddress((void**)&gfin,  g_gfin);
  cudaGetSymbolAddress((void**)&M,     g_M);

  // smem: sB[48][132] + sA[48][52] + tail(352 floats)
  constexpr int SM_T48 = (48 * 132 + 48 * 52 + 352) * 4;  // ~36.7 KB
  // gdfn smem
  constexpr int SM_GDFN =
      (48 * PXD + 32 * PXD + 16 * 132 + 48 * 36 + 16 * 52 + 32 * 10 +
       2 * PXD + 96) * 4;

  static bool attr_done = false;
  if (!attr_done) {
    cudaFuncSetAttribute(k_gdfn, cudaFuncAttributeMaxDynamicSharedMemorySize,
                         SM_GDFN);
    attr_done = true;
  }

  int gpix = Bb * Np / 128;  // 4096 pixel-blocks

  // 1. patch embed
  k_pe<<<Bb * Hh, 128>>>(x, pe_w, patch);

  // 2. LN(patch) -> qkv 1x1 (48 -> 144)
  k_tgemm<48, 48, 48, true, false, false><<<dim3(3, gpix), 192, SM_T48>>>(
      patch, Cc, 0, qkv_w, n1_w, n1_b, nullptr, 0, qkv0, C3, C3);

  // 3. depthwise 3x3 on qkv
  k_dw<<<(Bb * C3 * (Np / 4) + 255) / 256, 256>>>(qkv0, qkv_dw, qkv, C3);

  // 4-6. gram partials -> reduce -> softmax + fold po_w into M
  k_gram<<<Bb * NPART, 96>>>(qkv, part);
  k_red<<<(Bb * GSLOTS + 255) / 256, 256>>>(part, gfin);
  k_att<<<Bb, 256>>>(gfin, temp, po_w, M);

  // 7. first = patch + M @ v
  k_tgemm<48, 48, 48, false, true, true><<<dim3(1, gpix), 192, SM_T48>>>(
      qkv, C3, 96, M, nullptr, nullptr, patch, Cc, first, Cc, Cc);

  // 8. fused GDFN: out = first + ffn(LN2(first))
  k_gdfn<<<gpix, 192, SM_GDFN>>>(first, n2_w, n2_b, pi_w, ffn_dw, fo_w, out);
}

// round 4
// speedup vs baseline: 2.2110x; 2.2110x over previous
#include <cuda_runtime.h>
#include <cuda_fp16.h>
#include <math.h>
#include <stdint.h>

// ---------------------------------------------------------------------------
// Problem constants
// ---------------------------------------------------------------------------
namespace {
constexpr int Bb   = 2;
constexpr int Hh   = 512;
constexpr int Ww   = 512;
constexpr int Np   = Hh * Ww;
constexpr int Cc   = 48;
constexpr int C3   = 144;
constexpr int HID  = 127;
constexpr int HID2 = 254;
constexpr int NPART  = 1024;
constexpr int CHUNK  = Np / NPART;
constexpr int GSLOTS = 48 * 48 + 96;
}

// ---------------------------------------------------------------------------
// Scratch (fp16 for large intermediates, fp32 for residual-path tensors)
// ---------------------------------------------------------------------------
__device__ float  g_patch[(size_t)Bb * Cc * Np];
__device__ __half g_qkv0 [(size_t)Bb * C3 * Np];
__device__ __half g_qkv  [(size_t)Bb * C3 * Np];
__device__ float  g_first[(size_t)Bb * Cc * Np];
__device__ __half g_hbuf [(size_t)Bb * HID2 * Np];
__device__ __half g_gate [(size_t)Bb * HID * Np];
__device__ float  g_part [(size_t)Bb * NPART * GSLOTS];
__device__ float  g_gfin [Bb * GSLOTS];
__device__ float  g_M    [Bb * 48 * 48];

// ---------------------------------------------------------------------------
// tf32 helpers
// ---------------------------------------------------------------------------
__device__ __forceinline__ uint32_t f2tf(float f) {
  uint32_t r;
  asm("cvt.rna.tf32.f32 %0, %1;" : "=r"(r) : "f"(f));
  return r;
}
__device__ __forceinline__ void mma_tf32(float c[4], uint32_t a0, uint32_t a1,
                                         uint32_t a2, uint32_t a3, uint32_t b0,
                                         uint32_t b1) {
  asm volatile(
      "mma.sync.aligned.m16n8k8.row.col.f32.tf32.tf32.f32 "
      "{%0,%1,%2,%3}, {%4,%5,%6,%7}, {%8,%9}, {%0,%1,%2,%3};"
      : "+f"(c[0]), "+f"(c[1]), "+f"(c[2]), "+f"(c[3])
      : "r"(a0), "r"(a1), "r"(a2), "r"(a3), "r"(b0), "r"(b1));
}

// ---------------------------------------------------------------------------
// K1: patch embed conv 3x3, 3 -> 48 (fp32)
// ---------------------------------------------------------------------------
__global__ __launch_bounds__(128) void k_pe(const float* __restrict__ x,
                                            const float* __restrict__ pw,
                                            float* __restrict__ out) {
  __shared__ float ws[48 * 27];
  __shared__ float si[3][3][514];
  int b = blockIdx.x / Hh, y = blockIdx.x % Hh;
  int tid = threadIdx.x;
  for (int i = tid; i < 48 * 27; i += 128) ws[i] = pw[i];
  for (int i = tid; i < 3 * 3 * 512; i += 128) {
    int ch = i / 1536, r = (i / 512) % 3, xx = i % 512;
    int yy = y - 1 + r;
    float v = (yy >= 0 && yy < Hh)
                  ? x[((size_t)(b * 3 + ch) * Hh + yy) * Ww + xx]
                  : 0.f;
    si[ch][r][xx + 1] = v;
  }
  if (tid < 9) {
    int ch = tid / 3, r = tid % 3;
    si[ch][r][0] = 0.f;
    si[ch][r][513] = 0.f;
  }
  __syncthreads();

  int x0 = tid * 4;
  float rv[3][3][6];
#pragma unroll
  for (int ch = 0; ch < 3; ch++)
#pragma unroll
    for (int r = 0; r < 3; r++)
#pragma unroll
      for (int d = 0; d < 6; d++) rv[ch][r][d] = si[ch][r][x0 + d];

  float* op = out + (size_t)b * Cc * Np + (size_t)y * Ww + x0;
  for (int o = 0; o < 48; o++) {
    float a0 = 0.f, a1 = 0.f, a2 = 0.f, a3 = 0.f;
#pragma unroll
    for (int ch = 0; ch < 3; ch++)
#pragma unroll
      for (int r = 0; r < 3; r++)
#pragma unroll
        for (int dx = 0; dx < 3; dx++) {
          float w = ws[o * 27 + ch * 9 + r * 3 + dx];
          a0 = fmaf(rv[ch][r][dx + 0], w, a0);
          a1 = fmaf(rv[ch][r][dx + 1], w, a1);
          a2 = fmaf(rv[ch][r][dx + 2], w, a2);
          a3 = fmaf(rv[ch][r][dx + 3], w, a3);
        }
    *reinterpret_cast<float4*>(op + (size_t)o * Np) = make_float4(a0, a1, a2, a3);
  }
}

// ---------------------------------------------------------------------------
// Tensor-core pixel GEMM.  2-pass tf32: A = hi+lo (hoisted split, exact),
// B rounded once to tf32 (rna; exact when B comes from fp16).
// ---------------------------------------------------------------------------
template <int K, int KC, int BN, bool LN, bool RES, bool PBW, typename TIN,
          typename TOUT>
__global__ __launch_bounds__((BN / 16) * 64) void k_tgemm(
    const TIN* __restrict__ in, int in_cs, int in_co,
    const float* __restrict__ w, const float* __restrict__ nw,
    const float* __restrict__ nb, const float* __restrict__ res, int res_cs,
    TOUT* __restrict__ out, int out_cs, int CO) {
  constexpr int MT = BN / 16;
  constexpr int NTH = MT * 64;
  constexpr int SBd = 132;
  constexpr int SAd = BN + 4;
  constexpr int KSTEPS = KC / 8;

  extern __shared__ float smf[];
  float* sB = smf;                 // [KC][SBd]
  float* sA = smf + KC * SBd;      // [KC][SAd]
  float* tail = sA + KC * SAd;
  float* mu = tail;
  float* rs = tail + 128;
  float* snw = tail + 256;
  float* snb = tail + 304;

  int tid = threadIdx.x;
  int wid = tid / 32, lane = tid % 32;
  int warp_m = wid % MT, warp_n = wid / MT;
  int n0 = warp_n * 64;
  int o0 = blockIdx.x * BN;
  int pb = blockIdx.y;
  int b = pb / (Np / 128);
  int n0g = (pb % (Np / 128)) * 128;

  const TIN* ip = in + ((size_t)b * in_cs + in_co) * Np + n0g;
  const float* wp = PBW ? (w + (size_t)b * CO * K) : w;

  float acc[8][4];
#pragma unroll
  for (int j = 0; j < 8; j++)
#pragma unroll
    for (int i = 0; i < 4; i++) acc[j][i] = 0.f;

  for (int k0 = 0; k0 < K; k0 += KC) {
    for (int i = tid; i < KC * BN; i += NTH) {
      int k = i / BN, m = i % BN;
      int o = o0 + m, kk = k0 + k;
      sA[k * SAd + m] = (o < CO && kk < K) ? wp[(size_t)o * K + kk] : 0.f;
    }
    if constexpr (LN) {
      for (int i = tid; i < KC * 128; i += NTH) {
        int k = i >> 7, j = i & 127;
        sB[k * SBd + j] = (float)ip[(size_t)k * Np + j];
      }
      for (int i = tid; i < K; i += NTH) {
        snw[i] = nw[i];
        snb[i] = nb[i];
      }
      __syncthreads();
      for (int j = tid; j < 128; j += NTH) {
        float s = 0.f;
#pragma unroll 8
        for (int k = 0; k < K; k++) s += sB[k * SBd + j];
        float m = s * (1.f / (float)K);
        float v = 0.f;
#pragma unroll 8
        for (int k = 0; k < K; k++) {
          float d = sB[k * SBd + j] - m;
          v = fmaf(d, d, v);
        }
        mu[j] = m;
        rs[j] = rsqrtf(v * (1.f / (float)K) + 1e-5f);
      }
      __syncthreads();
      for (int i = tid; i < KC * 128; i += NTH) {
        int k = i >> 7, j = i & 127;
        sB[k * SBd + j] = (sB[k * SBd + j] - mu[j]) * rs[j] * snw[k] + snb[k];
      }
    } else if constexpr (sizeof(TIN) == 2) {
      // fp16 input: vectorized half2 staging
      for (int i = tid; i < KC * 64; i += NTH) {
        int k = i >> 6, j2 = i & 63;
        int kk = k0 + k;
        float2 f = make_float2(0.f, 0.f);
        if (kk < K) {
          __half2 h =
              *reinterpret_cast<const __half2*>(ip + (size_t)kk * Np + 2 * j2);
          f = __half22float2(h);
        }
        sB[k * SBd + 2 * j2] = f.x;
        sB[k * SBd + 2 * j2 + 1] = f.y;
      }
    } else {
      for (int i = tid; i < KC * 128; i += NTH) {
        int k = i >> 7, j = i & 127;
        int kk = k0 + k;
        sB[k * SBd + j] = (kk < K) ? (float)ip[(size_t)kk * Np + j] : 0.f;
      }
    }
    __syncthreads();

    int tg = lane & 3, gr = lane >> 2;
#pragma unroll
    for (int ks = 0; ks < KSTEPS; ks++) {
      int kr0 = ks * 8 + tg;
      float a0f = sA[kr0 * SAd + warp_m * 16 + gr];
      float a1f = sA[kr0 * SAd + warp_m * 16 + gr + 8];
      float a2f = sA[(kr0 + 4) * SAd + warp_m * 16 + gr];
      float a3f = sA[(kr0 + 4) * SAd + warp_m * 16 + gr + 8];
      uint32_t ah0 = f2tf(a0f), ah1 = f2tf(a1f), ah2 = f2tf(a2f),
               ah3 = f2tf(a3f);
      uint32_t al0 = f2tf(a0f - __uint_as_float(ah0));
      uint32_t al1 = f2tf(a1f - __uint_as_float(ah1));
      uint32_t al2 = f2tf(a2f - __uint_as_float(ah2));
      uint32_t al3 = f2tf(a3f - __uint_as_float(ah3));
#pragma unroll
      for (int j = 0; j < 8; j++) {
        float b0f = sB[kr0 * SBd + n0 + j * 8 + gr];
        float b1f = sB[(kr0 + 4) * SBd + n0 + j * 8 + gr];
        uint32_t bh0 = f2tf(b0f), bh1 = f2tf(b1f);
        mma_tf32(acc[j], ah0, ah1, ah2, ah3, bh0, bh1);
        mma_tf32(acc[j], al0, al1, al2, al3, bh0, bh1);
      }
    }
    if (k0 + KC < K) __syncthreads();
  }

  int gr = lane >> 2, tg = lane & 3;
#pragma unroll
  for (int j = 0; j < 8; j++) {
    int nn = n0 + j * 8 + 2 * tg;
#pragma unroll
    for (int h = 0; h < 2; h++) {
      int o = o0 + warp_m * 16 + gr + h * 8;
      if (o < CO) {
        float2 r = make_float2(acc[j][h * 2], acc[j][h * 2 + 1]);
        if constexpr (RES) {
          const float2 q = *reinterpret_cast<const float2*>(
              res + ((size_t)b * res_cs + o) * Np + n0g + nn);
          r.x += q.x;
          r.y += q.y;
        }
        if constexpr (sizeof(TOUT) == 2) {
          *reinterpret_cast<__half2*>(out + ((size_t)b * out_cs + o) * Np +
                                      n0g + nn) = __floats2half2_rn(r.x, r.y);
        } else {
          *reinterpret_cast<float2*>(out + ((size_t)b * out_cs + o) * Np +
                                     n0g + nn) = r;
        }
      }
    }
  }
}

// ---------------------------------------------------------------------------
// Depthwise 3x3 conv (SAME), fp16 in/out, 8 px per thread, fp32 math.
// ---------------------------------------------------------------------------
__global__ __launch_bounds__(256) void k_dw(const __half* __restrict__ in,
                                            const float* __restrict__ w9,
                                            __half* __restrict__ out, int Cn) {
  int idx = blockIdx.x * 256 + threadIdx.x;
  int total = Bb * Cn * Hh * (Ww / 8);
  if (idx >= total) return;
  int xq = idx % (Ww / 8);
  int t = idx / (Ww / 8);
  int y = t % Hh; t /= Hh;
  int c = t % Cn;
  int b = t / Cn;
  int x0 = xq * 8;

  float wv[9];
#pragma unroll
  for (int i = 0; i < 9; i++) wv[i] = w9[c * 9 + i];

  const __half* base = in + ((size_t)b * Cn + c) * Np;
  float a[8];
#pragma unroll
  for (int p = 0; p < 8; p++) a[p] = 0.f;

#pragma unroll
  for (int dy = 0; dy < 3; dy++) {
    int yy = y + dy - 1;
    if (yy < 0 || yy >= Hh) continue;
    const __half* row = base + (size_t)yy * Ww;
    float v[10];
    v[0] = (x0 > 0) ? __half2float(row[x0 - 1]) : 0.f;
    uint4 m = *reinterpret_cast<const uint4*>(row + x0);
    const __half2* hp = reinterpret_cast<const __half2*>(&m);
#pragma unroll
    for (int q = 0; q < 4; q++) {
      float2 f = __half22float2(hp[q]);
      v[1 + 2 * q] = f.x;
      v[2 + 2 * q] = f.y;
    }
    v[9] = (x0 + 8 < Ww) ? __half2float(row[x0 + 8]) : 0.f;
#pragma unroll
    for (int dx = 0; dx < 3; dx++) {
      float wt = wv[dy * 3 + dx];
#pragma unroll
      for (int p = 0; p < 8; p++) a[p] = fmaf(v[dx + p], wt, a[p]);
    }
  }
  __half2 o4[4];
#pragma unroll
  for (int q = 0; q < 4; q++) o4[q] = __floats2half2_rn(a[2 * q], a[2 * q + 1]);
  *reinterpret_cast<uint4*>(out + ((size_t)b * Cn + c) * Np + (size_t)y * Ww +
                            x0) = *reinterpret_cast<uint4*>(o4);
}

// ---------------------------------------------------------------------------
// GDFN: depthwise 3x3 on channels c and c+127, gelu gate, fp16 in/out.
// ---------------------------------------------------------------------------
__global__ __launch_bounds__(256) void k_dwgelu(const __half* __restrict__ in,
                                                const float* __restrict__ w9,
                                                __half* __restrict__ out) {
  int idx = blockIdx.x * 256 + threadIdx.x;
  int total = Bb * HID * Hh * (Ww / 8);
  if (idx >= total) return;
  int xq = idx % (Ww / 8);
  int t = idx / (Ww / 8);
  int y = t % Hh; t /= Hh;
  int c = t % HID;
  int b = t / HID;
  int x0 = xq * 8;

  float w1[9], w2[9];
#pragma unroll
  for (int i = 0; i < 9; i++) {
    w1[i] = w9[c * 9 + i];
    w2[i] = w9[(c + HID) * 9 + i];
  }
  const __half* b1 = in + ((size_t)b * HID2 + c) * Np;
  const __half* b2 = in + ((size_t)b * HID2 + c + HID) * Np;
  float a1[8], a2[8];
#pragma unroll
  for (int p = 0; p < 8; p++) {
    a1[p] = 0.f;
    a2[p] = 0.f;
  }
#pragma unroll
  for (int dy = 0; dy < 3; dy++) {
    int yy = y + dy - 1;
    if (yy < 0 || yy >= Hh) continue;
    const __half* r1 = b1 + (size_t)yy * Ww;
    const __half* r2 = b2 + (size_t)yy * Ww;
    float v1[10], v2[10];
    v1[0] = (x0 > 0) ? __half2float(r1[x0 - 1]) : 0.f;
    v2[0] = (x0 > 0) ? __half2float(r2[x0 - 1]) : 0.f;
    uint4 m1 = *reinterpret_cast<const uint4*>(r1 + x0);
    uint4 m2 = *reinterpret_cast<const uint4*>(r2 + x0);
    const __half2* h1 = reinterpret_cast<const __half2*>(&m1);
    const __half2* h2 = reinterpret_cast<const __half2*>(&m2);
#pragma unroll
    for (int q = 0; q < 4; q++) {
      float2 f1 = __half22float2(h1[q]);
      float2 f2 = __half22float2(h2[q]);
      v1[1 + 2 * q] = f1.x;
      v1[2 + 2 * q] = f1.y;
      v2[1 + 2 * q] = f2.x;
      v2[2 + 2 * q] = f2.y;
    }
    v1[9] = (x0 + 8 < Ww) ? __half2float(r1[x0 + 8]) : 0.f;
    v2[9] = (x0 + 8 < Ww) ? __half2float(r2[x0 + 8]) : 0.f;
#pragma unroll
    for (int dx = 0; dx < 3; dx++) {
      float wa = w1[dy * 3 + dx], wb = w2[dy * 3 + dx];
#pragma unroll
      for (int p = 0; p < 8; p++) {
        a1[p] = fmaf(v1[dx + p], wa, a1[p]);
        a2[p] = fmaf(v2[dx + p], wb, a2[p]);
      }
    }
  }
  __half2 o4[4];
#pragma unroll
  for (int q = 0; q < 4; q++) {
    float g0, g1;
    {
      float u = a1[2 * q];
      g0 = 0.5f * u * (1.f + erff(u * 0.70710678118654752f)) * a2[2 * q];
    }
    {
      float u = a1[2 * q + 1];
      g1 = 0.5f * u * (1.f + erff(u * 0.70710678118654752f)) * a2[2 * q + 1];
    }
    o4[q] = __floats2half2_rn(g0, g1);
  }
  *reinterpret_cast<uint4*>(out + ((size_t)b * HID + c) * Np + (size_t)y * Ww +
                            x0) = *reinterpret_cast<uint4*>(o4);
}

// ---------------------------------------------------------------------------
// Gram partials (fp16 input, fp32 accum; deterministic split-K)
// ---------------------------------------------------------------------------
__global__ __launch_bounds__(96) void k_gram(const __half* __restrict__ qkv,
                                             float* __restrict__ part) {
  __shared__ float sQ[48 * 33];
  __shared__ float sK[48 * 33];
  int blk = blockIdx.x;
  int b = blk / NPART, pc = blk % NPART;
  int n0 = pc * CHUNK;
  const __half* q = qkv + (size_t)b * C3 * Np;
  const __half* k = q + (size_t)48 * Np;
  int tid = threadIdx.x;
  int ct = tid / 12, dt = tid % 12;
  int c0 = ct * 6, d0 = dt * 4;

  float acc[6][4];
#pragma unroll
  for (int i = 0; i < 6; i++)
#pragma unroll
    for (int j = 0; j < 4; j++) acc[i][j] = 0.f;
  float nacc = 0.f;

  for (int t = 0; t < CHUNK / 32; t++) {
    int off = n0 + t * 32;
    __syncthreads();
    for (int i = tid; i < 48 * 16; i += 96) {
      int c = i / 16, j2 = i % 16;
      float2 fq = __half22float2(
          *reinterpret_cast<const __half2*>(q + (size_t)c * Np + off + 2 * j2));
      float2 fk = __half22float2(
          *reinterpret_cast<const __half2*>(k + (size_t)c * Np + off + 2 * j2));
      sQ[c * 33 + 2 * j2] = fq.x;
      sQ[c * 33 + 2 * j2 + 1] = fq.y;
      sK[c * 33 + 2 * j2] = fk.x;
      sK[c * 33 + 2 * j2 + 1] = fk.y;
    }
    __syncthreads();
#pragma unroll 4
    for (int j = 0; j < 32; j++) {
      float qa[6], kb[4];
#pragma unroll
      for (int i = 0; i < 6; i++) qa[i] = sQ[(c0 + i) * 33 + j];
#pragma unroll
      for (int i = 0; i < 4; i++) kb[i] = sK[(d0 + i) * 33 + j];
#pragma unroll
      for (int i = 0; i < 6; i++)
#pragma unroll
        for (int jj = 0; jj < 4; jj++)
          acc[i][jj] = fmaf(qa[i], kb[jj], acc[i][jj]);
    }
    {
      const float* s = (tid < 48) ? (sQ + tid * 33) : (sK + (tid - 48) * 33);
#pragma unroll 8
      for (int j = 0; j < 32; j++) {
        float v = s[j];
        nacc = fmaf(v, v, nacc);
      }
    }
  }
  float* pp = part + (size_t)blk * GSLOTS;
#pragma unroll
  for (int i = 0; i < 6; i++)
#pragma unroll
    for (int jj = 0; jj < 4; jj++) pp[(c0 + i) * 48 + d0 + jj] = acc[i][jj];
  pp[2304 + tid] = nacc;
}

__global__ void k_red(const float* __restrict__ part, float* __restrict__ gfin) {
  int s = blockIdx.x * blockDim.x + threadIdx.x;
  if (s >= Bb * GSLOTS) return;
  int b = s / GSLOTS, slot = s % GSLOTS;
  const float* p = part + (size_t)b * NPART * GSLOTS + slot;
  float a0 = 0.f, a1 = 0.f, a2 = 0.f, a3 = 0.f;
  for (int i = 0; i < NPART; i += 4) {
    a0 += p[(size_t)(i + 0) * GSLOTS];
    a1 += p[(size_t)(i + 1) * GSLOTS];
    a2 += p[(size_t)(i + 2) * GSLOTS];
    a3 += p[(size_t)(i + 3) * GSLOTS];
  }
  gfin[s] = (a0 + a1) + (a2 + a3);
}

__global__ __launch_bounds__(256) void k_att(const float* __restrict__ gfin,
                                             const float* __restrict__ temp,
                                             const float* __restrict__ po,
                                             float* __restrict__ M) {
  __shared__ float sG[2304];
  __shared__ float sAt[2304];
  __shared__ float snq[48], snk[48];
  int b = blockIdx.x, tid = threadIdx.x;
  const float* g = gfin + (size_t)b * GSLOTS;
  for (int i = tid; i < 2304; i += 256) sG[i] = g[i];
  if (tid < 96) {
    float nv = sqrtf(fmaxf(g[2304 + tid], 0.f));
    nv = fmaxf(nv, 1e-12f);
    if (tid < 48) snq[tid] = nv;
    else snk[tid - 48] = nv;
  }
  __syncthreads();
  float tv = temp[0];
  for (int i = tid; i < 2304; i += 256) {
    int c = i / 48, d = i % 48;
    sG[i] = sG[i] * tv / (snq[c] * snk[d]);
  }
  __syncthreads();
  if (tid < 48) {
    float mx = -1e30f;
    for (int d = 0; d < 48; d++) mx = fmaxf(mx, sG[tid * 48 + d]);
    float s = 0.f;
    for (int d = 0; d < 48; d++) {
      float e = expf(sG[tid * 48 + d] - mx);
      sAt[tid * 48 + d] = e;
      s += e;
    }
    float inv = 1.f / s;
    for (int d = 0; d < 48; d++) sAt[tid * 48 + d] *= inv;
  }
  __syncthreads();
  for (int i = tid; i < 2304; i += 256) {
    int o = i / 48, d = i % 48;
    float a = 0.f;
#pragma unroll 8
    for (int c = 0; c < 48; c++) a = fmaf(po[o * 48 + c], sAt[c * 48 + d], a);
    M[(size_t)b * 2304 + i] = a;
  }
}

// ---------------------------------------------------------------------------
// Launch
// ---------------------------------------------------------------------------
extern "C" void kernel_launch(void* const* d_in, const int* in_sizes, int n_in,
                              void* d_out, int out_size) {
  (void)in_sizes; (void)n_in; (void)out_size;
  const float* x      = (const float*)d_in[0];
  const float* pe_w   = (const float*)d_in[1];
  const float* n1_w   = (const float*)d_in[2];
  const float* n1_b   = (const float*)d_in[3];
  const float* temp   = (const float*)d_in[4];
  const float* qkv_w  = (const float*)d_in[5];
  const float* qkv_dw = (const float*)d_in[6];
  const float* po_w   = (const float*)d_in[7];
  const float* n2_w   = (const float*)d_in[8];
  const float* n2_b   = (const float*)d_in[9];
  const float* pi_w   = (const float*)d_in[10];
  const float* ffn_dw = (const float*)d_in[11];
  const float* fo_w   = (const float*)d_in[12];
  float* out = (float*)d_out;

  float *patch, *first, *part, *gfin, *M;
  __half *qkv0, *qkv, *hbuf, *gate;
  cudaGetSymbolAddress((void**)&patch, g_patch);
  cudaGetSymbolAddress((void**)&qkv0,  g_qkv0);
  cudaGetSymbolAddress((void**)&qkv,   g_qkv);
  cudaGetSymbolAddress((void**)&first, g_first);
  cudaGetSymbolAddress((void**)&hbuf,  g_hbuf);
  cudaGetSymbolAddress((void**)&gate,  g_gate);
  cudaGetSymbolAddress((void**)&part,  g_part);
  cudaGetSymbolAddress((void**)&gfin,  g_gfin);
  cudaGetSymbolAddress((void**)&M,     g_M);

  constexpr int SM_T48 = (48 * 132 + 48 * 52 + 352) * 4;  // 35.9 KB
  constexpr int SM_PI  = (48 * 132 + 48 * 68 + 352) * 4;  // 38.9 KB
  constexpr int SM_FO  = (64 * 132 + 64 * 52 + 352) * 4;  // 47.4 KB

  int gpix = Bb * Np / 128;  // 4096 pixel-blocks

  // 1. patch embed
  k_pe<<<Bb * Hh, 128>>>(x, pe_w, patch);

  // 2. LN(patch) -> qkv 1x1 (48 -> 144), fp16 out
  k_tgemm<48, 48, 48, true, false, false, float, __half>
      <<<dim3(3, gpix), 192, SM_T48>>>(patch, Cc, 0, qkv_w, n1_w, n1_b,
                                       nullptr, 0, qkv0, C3, C3);

  // 3. depthwise 3x3 on qkv (fp16)
  k_dw<<<(Bb * C3 * Hh * (Ww / 8) + 255) / 256, 256>>>(qkv0, qkv_dw, qkv, C3);

  // 4-6. gram partials -> reduce -> softmax + fold po_w into M
  k_gram<<<Bb * NPART, 96>>>(qkv, part);
  k_red<<<(Bb * GSLOTS + 255) / 256, 256>>>(part, gfin);
  k_att<<<Bb, 256>>>(gfin, temp, po_w, M);

  // 7. first = patch + M @ v   (v fp16 -> exact tf32 B)
  k_tgemm<48, 48, 48, false, true, true, __half, float>
      <<<dim3(1, gpix), 192, SM_T48>>>(qkv, C3, 96, M, nullptr, nullptr, patch,
                                       Cc, first, Cc, Cc);

  // 8. LN(first) -> pi 1x1 (48 -> 254), fp16 out
  k_tgemm<48, 48, 64, true, false, false, float, __half>
      <<<dim3(4, gpix), 256, SM_PI>>>(first, Cc, 0, pi_w, n2_w, n2_b, nullptr,
                                      0, hbuf, HID2, HID2);

  // 9. depthwise 3x3 + exact-gelu gating (254 -> 127), fp16
  k_dwgelu<<<(Bb * HID * Hh * (Ww / 8) + 255) / 256, 256>>>(hbuf, ffn_dw,
                                                            gate);

  // 10. out = first + fo 1x1 (127 -> 48)
  k_tgemm<127, 64, 48, false, true, false, __half, float>
      <<<dim3(1, gpix), 192, SM_FO>>>(gate, HID, 0, fo_w, nullptr, nullptr,
                                      first, Cc, out, Cc, Cc);
}